// round 14
// baseline (speedup 1.0000x reference)
#include <cuda_runtime.h>
#include <cuda_bf16.h>
#include <math.h>
#include <stdint.h>

// Problem constants
#define NTOK 16384
#define DIM  2048
#define NEXP 64
#define NK   (NTOK * 2)          // 32768 (token, slot) pairs

// GEMM tiling
#define BM 64                    // tokens per CTA
#define KC 32                    // fp32 per K-chunk (2 k16 MMA steps)
#define NCHUNK (DIM / KC)        // 64
#define GTHREADS 256             // 8 warps: warp tile M16 x N32
#define NBLK (NTOK / BM)         // 256 CTAs

// Output layout: concatenation of reference return values (all as fp32)
#define OFF_TOK   0
#define OFF_REV   NK
#define OFF_CW    (2 * NK)
#define OFF_SPL   (3 * NK)
#define OFF_PROBS (3 * NK + NEXP)

// smem stage layout (bytes): blocked 8x8-bf16 tiles (128B each).
#define AH_OFF 0
#define AL_OFF 4096
#define WH_OFF 8192
#define WL_OFF 12288
#define STAGE_BYTES 16384
#define SMEM_DYN (2 * STAGE_BYTES + 1024)

// Scratch (no allocations allowed -> __device__ globals)
__device__ int g_flat_idx[NK];
__device__ int g_blockHist[NBLK * NEXP];
__device__ int g_blockBase[NBLK * NEXP];

// ---------------------------------------------------------------------------
__device__ __forceinline__ uint32_t smem_u32(const void* p) {
    uint32_t a;
    asm("{ .reg .u64 t; cvta.to.shared.u64 t, %1; cvt.u32.u64 %0, t; }"
        : "=r"(a) : "l"(p));
    return a;
}

#define LDMX4(r0, r1, r2, r3, addr)                                           \
    asm volatile("ldmatrix.sync.aligned.m8n8.x4.shared.b16 {%0,%1,%2,%3}, [%4];" \
        : "=r"(r0), "=r"(r1), "=r"(r2), "=r"(r3) : "r"(addr))

#define MMA_BF16(c, a0, a1, a2, a3, b0, b1)                                   \
    asm volatile(                                                             \
        "mma.sync.aligned.m16n8k16.row.col.f32.bf16.bf16.f32 "                \
        "{%0,%1,%2,%3}, {%4,%5,%6,%7}, {%8,%9}, {%0,%1,%2,%3};"               \
        : "+f"((c)[0]), "+f"((c)[1]), "+f"((c)[2]), "+f"((c)[3])              \
        : "r"(a0), "r"(a1), "r"(a2), "r"(a3), "r"(b0), "r"(b1))

__device__ __forceinline__ uint32_t pack_bf16(__nv_bfloat16 a, __nv_bfloat16 b) {
    __nv_bfloat162 v; v.x = a; v.y = b;
    return *reinterpret_cast<uint32_t*>(&v);
}

__device__ __forceinline__ void split2(float x, float y, uint32_t& hi, uint32_t& lo) {
    __nv_bfloat16 hx = __float2bfloat16(x), hy = __float2bfloat16(y);
    float rx = x - __bfloat162float(hx);
    float ry = y - __bfloat162float(hy);
    hi = pack_bf16(hx, hy);
    lo = pack_bf16(__float2bfloat16(rx), __float2bfloat16(ry));
}

// split 8 floats -> 16B hi line + 16B lo line
__device__ __forceinline__ void split8(const float4& a, const float4& b,
                                       uint4& hi, uint4& lo) {
    split2(a.x, a.y, hi.x, lo.x);
    split2(a.z, a.w, hi.y, lo.y);
    split2(b.x, b.y, hi.z, lo.z);
    split2(b.z, b.w, hi.w, lo.w);
}

// ---------------------------------------------------------------------------
// Kernel 1: bf16-split mma.sync GEMM + softmax + top-2 + combine + probs +
// hist.  8 warps, warp tile M16 x N32.  Producer: one thread per (row, kt),
// STS.128 lines.  Consumer: all ldmatrix base addresses precomputed.
// ---------------------------------------------------------------------------
__global__ __launch_bounds__(GTHREADS, 2) void gate_gemm_kernel(
    const float* __restrict__ A,   // [NTOK, DIM]
    const float* __restrict__ W,   // [NEXP, DIM]
    float* __restrict__ out)
{
    extern __shared__ char dynsm[];
    char* sbase = (char*)(((uintptr_t)dynsm + 1023) & ~(uintptr_t)1023);
    const uint32_t sb = smem_u32(sbase);

    __shared__ int hist[NEXP];

    const int tid  = threadIdx.x;
    const int wid  = tid >> 5;
    const int lane = tid & 31;
    const int g    = lane >> 2;
    const int q    = lane & 3;
    const int lg   = lane >> 3;       // ldmatrix lane group 0..3
    const int lr   = lane & 7;
    const int mG   = wid >> 1;        // rows 16*mG  (0..3)
    const int nG   = wid & 1;         // cols 32*nG
    const int blk  = blockIdx.x;
    const int tok0 = blk * BM;

    if (tid < NEXP) hist[tid] = 0;

    // ---- producer geometry: thread = (row 0..63, kt 0..3) ------------------
    const int prow = tid & 63;
    const int pkt  = tid >> 6;        // 0..3

    const float4* Asrc = reinterpret_cast<const float4*>(
        A + (size_t)(tok0 + prow) * DIM + 8 * pkt);
    const float4* Wsrc = reinterpret_cast<const float4*>(
        W + (size_t)prow * DIM + 8 * pkt);
    const uint32_t pOff = (uint32_t)((pkt * 8 + (prow >> 3)) * 128 +
                                     (((prow & 7) ^ (pkt << 1)) << 4));

    float4 pa0, pa1, pw0, pw1;
    auto ldRegs = [&](int t) {
        const int o = t * 8;          // chunk stride = 32 floats = 8 float4
        pa0 = Asrc[o]; pa1 = Asrc[o + 1];
        pw0 = Wsrc[o]; pw1 = Wsrc[o + 1];
    };
    auto stStage = [&](int s) {
        char* stg = sbase + s * STAGE_BYTES;
        uint4 h, l;
        split8(pa0, pa1, h, l);
        *reinterpret_cast<uint4*>(stg + AH_OFF + pOff) = h;
        *reinterpret_cast<uint4*>(stg + AL_OFF + pOff) = l;
        split8(pw0, pw1, h, l);
        *reinterpret_cast<uint4*>(stg + WH_OFF + pOff) = h;
        *reinterpret_cast<uint4*>(stg + WL_OFF + pOff) = l;
    };

    float acc[4][4];
#pragma unroll
    for (int nt = 0; nt < 4; ++nt)
#pragma unroll
        for (int c = 0; c < 4; ++c) acc[nt][c] = 0.f;

    // ---- precomputed consumer addresses: [stage][ks] -----------------------
    const uint32_t aRt = (uint32_t)((2 * mG + (lg & 1)) * 128);
    const uint32_t wRt = (uint32_t)((4 * nG + (lg >> 1)) * 128);
    uint32_t aAddrT[2][2], wAddrT[2][2];
#pragma unroll
    for (int st = 0; st < 2; ++st)
#pragma unroll
        for (int ks = 0; ks < 2; ++ks) {
            const int ktA = 2 * ks + (lg >> 1);
            const int ktW = 2 * ks + (lg & 1);
            aAddrT[st][ks] = sb + (uint32_t)(st * STAGE_BYTES) +
                             (uint32_t)(ktA * 1024) +
                             (uint32_t)((lr ^ (ktA << 1)) << 4) + aRt;
            wAddrT[st][ks] = sb + (uint32_t)(st * STAGE_BYTES) + WH_OFF +
                             (uint32_t)(ktW * 1024) +
                             (uint32_t)((lr ^ (ktW << 1)) << 4) + wRt;
        }

    // prologue
    ldRegs(0);
    stStage(0);
    ldRegs(1);

#pragma unroll 1
    for (int tb = 0; tb < NCHUNK; tb += 2) {
#pragma unroll
        for (int tt = 0; tt < 2; ++tt) {
            const int t = tb + tt;
            __syncthreads();
            if (t + 1 < NCHUNK) {
                stStage(tt ^ 1);
                if (t + 2 < NCHUNK) ldRegs(t + 2);
            }
#pragma unroll
            for (int ks = 0; ks < 2; ++ks) {
                const uint32_t aAddr = aAddrT[tt][ks];
                const uint32_t wAddr = wAddrT[tt][ks];
                uint32_t ah[4], al[4], wh[8], wl[8];
                LDMX4(ah[0], ah[1], ah[2], ah[3], aAddr);
                LDMX4(al[0], al[1], al[2], al[3], aAddr + AL_OFF);
                LDMX4(wh[0], wh[1], wh[2], wh[3], wAddr);
                LDMX4(wh[4], wh[5], wh[6], wh[7], wAddr + 256);
                LDMX4(wl[0], wl[1], wl[2], wl[3], wAddr + 4096);
                LDMX4(wl[4], wl[5], wl[6], wl[7], wAddr + 4096 + 256);
#pragma unroll
                for (int nt = 0; nt < 4; ++nt) {
                    const uint32_t bh0 = wh[2 * nt], bh1 = wh[2 * nt + 1];
                    const uint32_t bl0 = wl[2 * nt], bl1 = wl[2 * nt + 1];
                    MMA_BF16(acc[nt], ah[0], ah[1], ah[2], ah[3], bh0, bh1);
                    MMA_BF16(acc[nt], ah[0], ah[1], ah[2], ah[3], bl0, bl1);
                    MMA_BF16(acc[nt], al[0], al[1], al[2], al[3], bh0, bh1);
                }
            }
        }
    }

    // ---- epilogue: logits -> Cs (reuse stage smem) -------------------------
    __syncthreads();
    float* Cs = reinterpret_cast<float*>(sbase);      // [64][66]
#pragma unroll
    for (int nt = 0; nt < 4; ++nt) {
        int row = 16 * mG + g;
        int col = 32 * nG + 8 * nt + 2 * q;
        *reinterpret_cast<float2*>(&Cs[row * 66 + col]) =
            make_float2(acc[nt][0], acc[nt][1]);
        *reinterpret_cast<float2*>(&Cs[(row + 8) * 66 + col]) =
            make_float2(acc[nt][2], acc[nt][3]);
    }
    __syncthreads();

    if (tid < BM) {                     // one thread per token
        const int t = tid;
        float f[64];
        float mx = -1e30f;
#pragma unroll
        for (int e = 0; e < NEXP; e++) { f[e] = Cs[t * 66 + e]; mx = fmaxf(mx, f[e]); }
        float ssum = 0.f;
#pragma unroll
        for (int e = 0; e < NEXP; e++) { f[e] = expf(f[e] - mx); ssum += f[e]; }
        float inv = 1.0f / ssum;
        float v1 = -1.f, v2 = -1.f;
        int i1 = 0, i2 = 0;
#pragma unroll
        for (int e = 0; e < NEXP; e++) {
            float p = f[e] * inv;
            Cs[t * 66 + e] = p;         // probs back to smem for coalesced copy
            if (p > v1)      { v2 = v1; i2 = i1; v1 = p; i1 = e; }
            else if (p > v2) { v2 = p; i2 = e; }
        }
        // combine = softmax over the top-2 prob VALUES (reference quirk)
        float eb = expf(v2 - v1);
        float invd = 1.0f / (1.0f + eb);
        const int token = tok0 + t;
        const int flat = token * 2;
        out[OFF_CW + flat]     = invd;
        out[OFF_CW + flat + 1] = eb * invd;
        g_flat_idx[flat]     = i1;
        g_flat_idx[flat + 1] = i2;
        atomicAdd(&hist[i1], 1);
        atomicAdd(&hist[i2], 1);
    }
    __syncthreads();

    if (tid < NEXP) g_blockHist[blk * NEXP + tid] = hist[tid];

    // coalesced probs writeback
    float* pout = out + OFF_PROBS + (size_t)tok0 * NEXP;
    for (int idx = tid; idx < BM * NEXP; idx += GTHREADS) {
        int tt = idx >> 6, e = idx & 63;
        pout[idx] = Cs[tt * 66 + e];
    }
}

// ---------------------------------------------------------------------------
// Kernel 2 (1 CTA, 1024 threads): per-expert scan across blocks + offsets
// ---------------------------------------------------------------------------
#define CHUNKB (NBLK / 16)       // 16 blocks per chunk
__global__ __launch_bounds__(1024) void gate_scan_kernel(float* __restrict__ out)
{
    __shared__ int part[16][NEXP];
    __shared__ int totals[NEXP];
    __shared__ int offs[NEXP];
    const int tid = threadIdx.x;
    const int e = tid & 63;
    const int c = tid >> 6;          // chunk 0..15

    int s = 0;
#pragma unroll
    for (int b = c * CHUNKB; b < (c + 1) * CHUNKB; b++) s += g_blockHist[b * NEXP + e];
    part[c][e] = s;
    __syncthreads();

    if (tid < NEXP) {
        int run = 0;
#pragma unroll
        for (int cc = 0; cc < 16; cc++) run += part[cc][e];
        totals[e] = run;
        out[OFF_SPL + e] = (float)run;
    }
    __syncthreads();

    if (tid == 0) {
        int a = 0;
        for (int i = 0; i < NEXP; i++) { offs[i] = a; a += totals[i]; }
    }
    __syncthreads();

    int base = offs[e];
    for (int cc = 0; cc < c; cc++) base += part[cc][e];
#pragma unroll
    for (int b = c * CHUNKB; b < (c + 1) * CHUNKB; b++) {
        g_blockBase[b * NEXP + e] = base;
        base += g_blockHist[b * NEXP + e];
    }
}

// ---------------------------------------------------------------------------
// Kernel 3 (NBLK x 128): stable intra-block rank + scatter.
// ---------------------------------------------------------------------------
__global__ __launch_bounds__(128) void gate_scatter_kernel(float* __restrict__ out)
{
    __shared__ int warpHist[4][NEXP];
    __shared__ int base_s[NEXP];
    const int tid  = threadIdx.x;
    const int blk  = blockIdx.x;
    const int w    = tid >> 5;
    const int lane = tid & 31;

    if (tid < NEXP) base_s[tid] = g_blockBase[blk * NEXP + tid];
    for (int i = tid; i < 4 * NEXP; i += 128) (&warpHist[0][0])[i] = 0;
    __syncthreads();

    const int flat = blk * 128 + tid;
    const int e    = g_flat_idx[flat];

    unsigned m     = __match_any_sync(0xffffffffu, e);
    unsigned below = m & ((1u << lane) - 1u);
    int rank = __popc(below);
    if (below == 0) warpHist[w][e] = __popc(m);     // lowest lane of group
    __syncthreads();

    int prev = 0;
#pragma unroll
    for (int ww = 0; ww < 3; ++ww)
        if (ww < w) prev += warpHist[ww][e];

    const int pos = base_s[e] + prev + rank;
    out[OFF_TOK + pos]  = (float)(flat >> 1);       // token index
    out[OFF_REV + flat] = (float)pos;               // sorted position of flat idx
}

// ---------------------------------------------------------------------------
extern "C" void kernel_launch(void* const* d_in, const int* in_sizes, int n_in,
                              void* d_out, int out_size)
{
    const float* A = (const float*)d_in[0];   // inputs    [16384, 2048] fp32
    const float* W = (const float*)d_in[1];   // wg_weight [64, 2048]    fp32
    float* out = (float*)d_out;

    cudaFuncSetAttribute(gate_gemm_kernel,
                         cudaFuncAttributeMaxDynamicSharedMemorySize, SMEM_DYN);

    gate_gemm_kernel<<<NBLK, GTHREADS, SMEM_DYN>>>(A, W, out);
    gate_scan_kernel<<<1, 1024>>>(out);
    gate_scatter_kernel<<<NK / 128, 128>>>(out);
}

// round 15
// speedup vs baseline: 1.7232x; 1.7232x over previous
#include <cuda_runtime.h>
#include <cuda_bf16.h>
#include <math.h>
#include <stdint.h>

// Problem constants
#define NTOK 16384
#define DIM  2048
#define NEXP 64
#define NK   (NTOK * 2)          // 32768 (token, slot) pairs

// GEMM tiling
#define BM 64                    // tokens per CTA
#define KC 32                    // fp32 per K-chunk (2 k16 MMA steps)
#define NCHUNK (DIM / KC)        // 64
#define GTHREADS 256             // 8 warps: warp tile M16 x N32
#define NBLK (NTOK / BM)         // 256 CTAs

// Output layout: concatenation of reference return values (all as fp32)
#define OFF_TOK   0
#define OFF_REV   NK
#define OFF_CW    (2 * NK)
#define OFF_SPL   (3 * NK)
#define OFF_PROBS (3 * NK + NEXP)

// smem stage layout (bytes): blocked 8x8-bf16 tiles (128B each).
#define AH_OFF 0
#define AL_OFF 4096
#define WH_OFF 8192
#define WL_OFF 12288
#define STAGE_BYTES 16384
#define SMEM_DYN (2 * STAGE_BYTES + 1024)

// Scratch (no allocations allowed -> __device__ globals)
__device__ int g_flat_idx[NK];
__device__ int g_blockHist[NBLK * NEXP];
__device__ int g_blockBase[NBLK * NEXP];

// ---------------------------------------------------------------------------
__device__ __forceinline__ uint32_t smem_u32(const void* p) {
    uint32_t a;
    asm("{ .reg .u64 t; cvta.to.shared.u64 t, %1; cvt.u32.u64 %0, t; }"
        : "=r"(a) : "l"(p));
    return a;
}

#define LDMX4(r0, r1, r2, r3, addr)                                           \
    asm volatile("ldmatrix.sync.aligned.m8n8.x4.shared.b16 {%0,%1,%2,%3}, [%4];" \
        : "=r"(r0), "=r"(r1), "=r"(r2), "=r"(r3) : "r"(addr))

#define MMA_BF16(c, a0, a1, a2, a3, b0, b1)                                   \
    asm volatile(                                                             \
        "mma.sync.aligned.m16n8k16.row.col.f32.bf16.bf16.f32 "                \
        "{%0,%1,%2,%3}, {%4,%5,%6,%7}, {%8,%9}, {%0,%1,%2,%3};"               \
        : "+f"((c)[0]), "+f"((c)[1]), "+f"((c)[2]), "+f"((c)[3])              \
        : "r"(a0), "r"(a1), "r"(a2), "r"(a3), "r"(b0), "r"(b1))

__device__ __forceinline__ uint32_t pack_bf16(__nv_bfloat16 a, __nv_bfloat16 b) {
    __nv_bfloat162 v; v.x = a; v.y = b;
    return *reinterpret_cast<uint32_t*>(&v);
}

__device__ __forceinline__ void split2(float x, float y, uint32_t& hi, uint32_t& lo) {
    __nv_bfloat16 hx = __float2bfloat16(x), hy = __float2bfloat16(y);
    float rx = x - __bfloat162float(hx);
    float ry = y - __bfloat162float(hy);
    hi = pack_bf16(hx, hy);
    lo = pack_bf16(__float2bfloat16(rx), __float2bfloat16(ry));
}

// ---------------------------------------------------------------------------
// Kernel 1: bf16-split mma.sync GEMM + softmax + top-2 + combine + probs +
// hist.  8 warps, warp tile M16 x N32.  Producer geometry = R13 (coalesced:
// 4 rows x 128B per warp LDG).  Consumer: ldmatrix addresses precomputed,
// mainloop unrolled x2 so stage indices are literals.
// ---------------------------------------------------------------------------
__global__ __launch_bounds__(GTHREADS, 2) void gate_gemm_kernel(
    const float* __restrict__ A,   // [NTOK, DIM]
    const float* __restrict__ W,   // [NEXP, DIM]
    float* __restrict__ out)
{
    extern __shared__ char dynsm[];
    char* sbase = (char*)(((uintptr_t)dynsm + 1023) & ~(uintptr_t)1023);
    const uint32_t sb = smem_u32(sbase);

    __shared__ int hist[NEXP];

    const int tid  = threadIdx.x;
    const int wid  = tid >> 5;
    const int lane = tid & 31;
    const int g    = lane >> 2;
    const int q    = lane & 3;
    const int lg   = lane >> 3;       // ldmatrix lane group 0..3
    const int lr   = lane & 7;
    const int mG   = wid >> 1;        // rows 16*mG  (0..3)
    const int nG   = wid & 1;         // cols 32*nG
    const int blk  = blockIdx.x;
    const int tok0 = blk * BM;

    if (tid < NEXP) hist[tid] = 0;

    // ---- producer geometry (R13): 256 threads, 2 rows each -----------------
    const int prow = tid >> 3;        // 0..31
    const int c4   = tid & 7;
    const int kt_p = c4 >> 1;
    const int hf_p = c4 & 1;

    const float4* Ap[2];
    const float4* Wp[2];
    uint32_t stOff[2];
#pragma unroll
    for (int p = 0; p < 2; ++p) {
        int r = prow + 32 * p;        // 0..63
        Ap[p] = reinterpret_cast<const float4*>(A + (size_t)(tok0 + r) * DIM + 4 * c4);
        Wp[p] = reinterpret_cast<const float4*>(W + (size_t)r * DIM + 4 * c4);
        stOff[p] = (uint32_t)((kt_p * 8 + (r >> 3)) * 128 +
                              (((r & 7) ^ (kt_p << 1)) << 4) + hf_p * 8);
    }

    float4 pa[2], pw[2];
    auto ldRegs = [&](int t) {
        const int o = t * 8;          // 32 floats = 8 float4
#pragma unroll
        for (int p = 0; p < 2; ++p) { pa[p] = Ap[p][o]; pw[p] = Wp[p][o]; }
    };
    auto stStage = [&](int s) {
        char* stg = sbase + s * STAGE_BYTES;
#pragma unroll
        for (int p = 0; p < 2; ++p) {
            uint2 h, l;
            split2(pa[p].x, pa[p].y, h.x, l.x);
            split2(pa[p].z, pa[p].w, h.y, l.y);
            *reinterpret_cast<uint2*>(stg + AH_OFF + stOff[p]) = h;
            *reinterpret_cast<uint2*>(stg + AL_OFF + stOff[p]) = l;
            split2(pw[p].x, pw[p].y, h.x, l.x);
            split2(pw[p].z, pw[p].w, h.y, l.y);
            *reinterpret_cast<uint2*>(stg + WH_OFF + stOff[p]) = h;
            *reinterpret_cast<uint2*>(stg + WL_OFF + stOff[p]) = l;
        }
    };

    float acc[4][4];
#pragma unroll
    for (int nt = 0; nt < 4; ++nt)
#pragma unroll
        for (int c = 0; c < 4; ++c) acc[nt][c] = 0.f;

    // ---- precomputed consumer addresses: [stage][ks] -----------------------
    const uint32_t aRt = (uint32_t)((2 * mG + (lg & 1)) * 128);
    const uint32_t wRt = (uint32_t)((4 * nG + (lg >> 1)) * 128);
    uint32_t aAddrT[2][2], wAddrT[2][2];
#pragma unroll
    for (int st = 0; st < 2; ++st)
#pragma unroll
        for (int ks = 0; ks < 2; ++ks) {
            const int ktA = 2 * ks + (lg >> 1);
            const int ktW = 2 * ks + (lg & 1);
            aAddrT[st][ks] = sb + (uint32_t)(st * STAGE_BYTES) +
                             (uint32_t)(ktA * 1024) +
                             (uint32_t)((lr ^ (ktA << 1)) << 4) + aRt;
            wAddrT[st][ks] = sb + (uint32_t)(st * STAGE_BYTES) + WH_OFF +
                             (uint32_t)(ktW * 1024) +
                             (uint32_t)((lr ^ (ktW << 1)) << 4) + wRt;
        }

    // prologue
    ldRegs(0);
    stStage(0);
    ldRegs(1);

#pragma unroll 1
    for (int tb = 0; tb < NCHUNK; tb += 2) {
#pragma unroll
        for (int tt = 0; tt < 2; ++tt) {
            const int t = tb + tt;
            __syncthreads();
            if (t + 1 < NCHUNK) {
                stStage(tt ^ 1);
                if (t + 2 < NCHUNK) ldRegs(t + 2);
            }
#pragma unroll
            for (int ks = 0; ks < 2; ++ks) {
                const uint32_t aAddr = aAddrT[tt][ks];
                const uint32_t wAddr = wAddrT[tt][ks];
                uint32_t ah[4], al[4], wh[8], wl[8];
                LDMX4(ah[0], ah[1], ah[2], ah[3], aAddr);
                LDMX4(al[0], al[1], al[2], al[3], aAddr + AL_OFF);
                LDMX4(wh[0], wh[1], wh[2], wh[3], wAddr);
                LDMX4(wh[4], wh[5], wh[6], wh[7], wAddr + 256);
                LDMX4(wl[0], wl[1], wl[2], wl[3], wAddr + 4096);
                LDMX4(wl[4], wl[5], wl[6], wl[7], wAddr + 4096 + 256);
#pragma unroll
                for (int nt = 0; nt < 4; ++nt) {
                    const uint32_t bh0 = wh[2 * nt], bh1 = wh[2 * nt + 1];
                    const uint32_t bl0 = wl[2 * nt], bl1 = wl[2 * nt + 1];
                    MMA_BF16(acc[nt], ah[0], ah[1], ah[2], ah[3], bh0, bh1);
                    MMA_BF16(acc[nt], ah[0], ah[1], ah[2], ah[3], bl0, bl1);
                    MMA_BF16(acc[nt], al[0], al[1], al[2], al[3], bh0, bh1);
                }
            }
        }
    }

    // ---- epilogue: logits -> Cs (reuse stage smem) -------------------------
    __syncthreads();
    float* Cs = reinterpret_cast<float*>(sbase);      // [64][66]
#pragma unroll
    for (int nt = 0; nt < 4; ++nt) {
        int row = 16 * mG + g;
        int col = 32 * nG + 8 * nt + 2 * q;
        *reinterpret_cast<float2*>(&Cs[row * 66 + col]) =
            make_float2(acc[nt][0], acc[nt][1]);
        *reinterpret_cast<float2*>(&Cs[(row + 8) * 66 + col]) =
            make_float2(acc[nt][2], acc[nt][3]);
    }
    __syncthreads();

    if (tid < BM) {                     // one thread per token
        const int t = tid;
        float f[64];
        float mx = -1e30f;
#pragma unroll
        for (int e = 0; e < NEXP; e++) { f[e] = Cs[t * 66 + e]; mx = fmaxf(mx, f[e]); }
        float ssum = 0.f;
#pragma unroll
        for (int e = 0; e < NEXP; e++) { f[e] = expf(f[e] - mx); ssum += f[e]; }
        float inv = 1.0f / ssum;
        float v1 = -1.f, v2 = -1.f;
        int i1 = 0, i2 = 0;
#pragma unroll
        for (int e = 0; e < NEXP; e++) {
            float p = f[e] * inv;
            Cs[t * 66 + e] = p;         // probs back to smem for coalesced copy
            if (p > v1)      { v2 = v1; i2 = i1; v1 = p; i1 = e; }
            else if (p > v2) { v2 = p; i2 = e; }
        }
        // combine = softmax over the top-2 prob VALUES (reference quirk)
        float eb = expf(v2 - v1);
        float invd = 1.0f / (1.0f + eb);
        const int token = tok0 + t;
        const int flat = token * 2;
        out[OFF_CW + flat]     = invd;
        out[OFF_CW + flat + 1] = eb * invd;
        g_flat_idx[flat]     = i1;
        g_flat_idx[flat + 1] = i2;
        atomicAdd(&hist[i1], 1);
        atomicAdd(&hist[i2], 1);
    }
    __syncthreads();

    if (tid < NEXP) g_blockHist[blk * NEXP + tid] = hist[tid];

    // coalesced probs writeback
    float* pout = out + OFF_PROBS + (size_t)tok0 * NEXP;
    for (int idx = tid; idx < BM * NEXP; idx += GTHREADS) {
        int tt = idx >> 6, e = idx & 63;
        pout[idx] = Cs[tt * 66 + e];
    }
}

// ---------------------------------------------------------------------------
// Kernel 2 (1 CTA, 1024 threads): per-expert scan across blocks + offsets
// ---------------------------------------------------------------------------
#define CHUNKB (NBLK / 16)       // 16 blocks per chunk
__global__ __launch_bounds__(1024) void gate_scan_kernel(float* __restrict__ out)
{
    __shared__ int part[16][NEXP];
    __shared__ int totals[NEXP];
    __shared__ int offs[NEXP];
    const int tid = threadIdx.x;
    const int e = tid & 63;
    const int c = tid >> 6;          // chunk 0..15

    int s = 0;
#pragma unroll
    for (int b = c * CHUNKB; b < (c + 1) * CHUNKB; b++) s += g_blockHist[b * NEXP + e];
    part[c][e] = s;
    __syncthreads();

    if (tid < NEXP) {
        int run = 0;
#pragma unroll
        for (int cc = 0; cc < 16; cc++) run += part[cc][e];
        totals[e] = run;
        out[OFF_SPL + e] = (float)run;
    }
    __syncthreads();

    if (tid == 0) {
        int a = 0;
        for (int i = 0; i < NEXP; i++) { offs[i] = a; a += totals[i]; }
    }
    __syncthreads();

    int base = offs[e];
    for (int cc = 0; cc < c; cc++) base += part[cc][e];
#pragma unroll
    for (int b = c * CHUNKB; b < (c + 1) * CHUNKB; b++) {
        g_blockBase[b * NEXP + e] = base;
        base += g_blockHist[b * NEXP + e];
    }
}

// ---------------------------------------------------------------------------
// Kernel 3 (NBLK x 128): stable intra-block rank + scatter.
// ---------------------------------------------------------------------------
__global__ __launch_bounds__(128) void gate_scatter_kernel(float* __restrict__ out)
{
    __shared__ int warpHist[4][NEXP];
    __shared__ int base_s[NEXP];
    const int tid  = threadIdx.x;
    const int blk  = blockIdx.x;
    const int w    = tid >> 5;
    const int lane = tid & 31;

    if (tid < NEXP) base_s[tid] = g_blockBase[blk * NEXP + tid];
    for (int i = tid; i < 4 * NEXP; i += 128) (&warpHist[0][0])[i] = 0;
    __syncthreads();

    const int flat = blk * 128 + tid;
    const int e    = g_flat_idx[flat];

    unsigned m     = __match_any_sync(0xffffffffu, e);
    unsigned below = m & ((1u << lane) - 1u);
    int rank = __popc(below);
    if (below == 0) warpHist[w][e] = __popc(m);     // lowest lane of group
    __syncthreads();

    int prev = 0;
#pragma unroll
    for (int ww = 0; ww < 3; ++ww)
        if (ww < w) prev += warpHist[ww][e];

    const int pos = base_s[e] + prev + rank;
    out[OFF_TOK + pos]  = (float)(flat >> 1);       // token index
    out[OFF_REV + flat] = (float)pos;               // sorted position of flat idx
}

// ---------------------------------------------------------------------------
extern "C" void kernel_launch(void* const* d_in, const int* in_sizes, int n_in,
                              void* d_out, int out_size)
{
    const float* A = (const float*)d_in[0];   // inputs    [16384, 2048] fp32
    const float* W = (const float*)d_in[1];   // wg_weight [64, 2048]    fp32
    float* out = (float*)d_out;

    cudaFuncSetAttribute(gate_gemm_kernel,
                         cudaFuncAttributeMaxDynamicSharedMemorySize, SMEM_DYN);

    gate_gemm_kernel<<<NBLK, GTHREADS, SMEM_DYN>>>(A, W, out);
    gate_scan_kernel<<<1, 1024>>>(out);
    gate_scatter_kernel<<<NK / 128, 128>>>(out);
}

// round 16
// speedup vs baseline: 1.7879x; 1.0375x over previous
#include <cuda_runtime.h>
#include <cuda_bf16.h>
#include <math.h>
#include <stdint.h>

// Problem constants
#define NTOK 16384
#define DIM  2048
#define NEXP 64
#define NK   (NTOK * 2)          // 32768 (token, slot) pairs

// GEMM tiling
#define BM 64                    // tokens per CTA
#define KC 32                    // fp32 per K-chunk (2 k16 steps, one per warp group)
#define NCHUNK (DIM / KC)        // 64
#define GTHREADS 256             // 8 warps: (ks, mG, nG) each M32 x N32 x k16
#define NBLK (NTOK / BM)         // 256 CTAs

// Output layout: concatenation of reference return values (all as fp32)
#define OFF_TOK   0
#define OFF_REV   NK
#define OFF_CW    (2 * NK)
#define OFF_SPL   (3 * NK)
#define OFF_PROBS (3 * NK + NEXP)

// smem stage layout (bytes): blocked 8x8-bf16 tiles (128B each).
#define AH_OFF 0
#define AL_OFF 4096
#define WH_OFF 8192
#define WL_OFF 12288
#define STAGE_BYTES 16384
#define SMEM_DYN (2 * STAGE_BYTES + 2048)

// Scratch (no allocations allowed -> __device__ globals)
__device__ int g_flat_idx[NK];
__device__ int g_blockHist[NBLK * NEXP];
__device__ int g_blockBase[NBLK * NEXP];

// ---------------------------------------------------------------------------
__device__ __forceinline__ uint32_t smem_u32(const void* p) {
    uint32_t a;
    asm("{ .reg .u64 t; cvta.to.shared.u64 t, %1; cvt.u32.u64 %0, t; }"
        : "=r"(a) : "l"(p));
    return a;
}

#define LDMX4(r0, r1, r2, r3, addr)                                           \
    asm volatile("ldmatrix.sync.aligned.m8n8.x4.shared.b16 {%0,%1,%2,%3}, [%4];" \
        : "=r"(r0), "=r"(r1), "=r"(r2), "=r"(r3) : "r"(addr))

#define MMA_BF16(c, a0, a1, a2, a3, b0, b1)                                   \
    asm volatile(                                                             \
        "mma.sync.aligned.m16n8k16.row.col.f32.bf16.bf16.f32 "                \
        "{%0,%1,%2,%3}, {%4,%5,%6,%7}, {%8,%9}, {%0,%1,%2,%3};"               \
        : "+f"((c)[0]), "+f"((c)[1]), "+f"((c)[2]), "+f"((c)[3])              \
        : "r"(a0), "r"(a1), "r"(a2), "r"(a3), "r"(b0), "r"(b1))

__device__ __forceinline__ uint32_t pack_bf16(__nv_bfloat16 a, __nv_bfloat16 b) {
    __nv_bfloat162 v; v.x = a; v.y = b;
    return *reinterpret_cast<uint32_t*>(&v);
}

__device__ __forceinline__ void split2(float x, float y, uint32_t& hi, uint32_t& lo) {
    __nv_bfloat16 hx = __float2bfloat16(x), hy = __float2bfloat16(y);
    float rx = x - __bfloat162float(hx);
    float ry = y - __bfloat162float(hy);
    hi = pack_bf16(hx, hy);
    lo = pack_bf16(__float2bfloat16(rx), __float2bfloat16(ry));
}

// ---------------------------------------------------------------------------
// Kernel 1: ks-split bf16 GEMM.  8 warps = (ks = wid>>2) x (mG = (wid>>1)&1)
// x (nG = wid&1).  Each warp: M32 x N32 x its own k16 half of every chunk.
// Per-warp LDSM traffic = R6 level; warps/SM = R13 level.
// ---------------------------------------------------------------------------
__global__ __launch_bounds__(GTHREADS, 2) void gate_gemm_kernel(
    const float* __restrict__ A,   // [NTOK, DIM]
    const float* __restrict__ W,   // [NEXP, DIM]
    float* __restrict__ out)
{
    extern __shared__ char dynsm[];
    char* sbase = (char*)(((uintptr_t)dynsm + 1023) & ~(uintptr_t)1023);
    const uint32_t sb = smem_u32(sbase);

    __shared__ int hist[NEXP];

    const int tid  = threadIdx.x;
    const int wid  = tid >> 5;
    const int lane = tid & 31;
    const int g    = lane >> 2;
    const int q    = lane & 3;
    const int lg   = lane >> 3;       // ldmatrix lane group 0..3
    const int lr   = lane & 7;
    const int ks   = wid >> 2;        // k16 half owned by this warp
    const int mG   = (wid >> 1) & 1;  // rows 32*mG
    const int nG   = wid & 1;         // cols 32*nG
    const int blk  = blockIdx.x;
    const int tok0 = blk * BM;

    if (tid < NEXP) hist[tid] = 0;

    // ---- producer geometry (R13/R15, proven coalesced) ---------------------
    const int prow = tid >> 3;        // 0..31
    const int c4   = tid & 7;
    const int kt_p = c4 >> 1;
    const int hf_p = c4 & 1;

    const float4* Ap[2];
    const float4* Wp[2];
    uint32_t stOff[2];
#pragma unroll
    for (int p = 0; p < 2; ++p) {
        int r = prow + 32 * p;        // 0..63
        Ap[p] = reinterpret_cast<const float4*>(A + (size_t)(tok0 + r) * DIM + 4 * c4);
        Wp[p] = reinterpret_cast<const float4*>(W + (size_t)r * DIM + 4 * c4);
        stOff[p] = (uint32_t)((kt_p * 8 + (r >> 3)) * 128 +
                              (((r & 7) ^ (kt_p << 1)) << 4) + hf_p * 8);
    }

    float4 pa[2], pw[2];
    auto ldRegs = [&](int t) {
        const int o = t * 8;          // 32 floats = 8 float4
#pragma unroll
        for (int p = 0; p < 2; ++p) { pa[p] = Ap[p][o]; pw[p] = Wp[p][o]; }
    };
    auto stStage = [&](int s) {
        char* stg = sbase + s * STAGE_BYTES;
#pragma unroll
        for (int p = 0; p < 2; ++p) {
            uint2 h, l;
            split2(pa[p].x, pa[p].y, h.x, l.x);
            split2(pa[p].z, pa[p].w, h.y, l.y);
            *reinterpret_cast<uint2*>(stg + AH_OFF + stOff[p]) = h;
            *reinterpret_cast<uint2*>(stg + AL_OFF + stOff[p]) = l;
            split2(pw[p].x, pw[p].y, h.x, l.x);
            split2(pw[p].z, pw[p].w, h.y, l.y);
            *reinterpret_cast<uint2*>(stg + WH_OFF + stOff[p]) = h;
            *reinterpret_cast<uint2*>(stg + WL_OFF + stOff[p]) = l;
        }
    };

    float acc[2][4][4];               // [mt][nt][c]
#pragma unroll
    for (int mt = 0; mt < 2; ++mt)
#pragma unroll
        for (int nt = 0; nt < 4; ++nt)
#pragma unroll
            for (int c = 0; c < 4; ++c) acc[mt][nt][c] = 0.f;

    // ---- precomputed consumer addresses (ks fixed per warp): [stage] -------
    const int ktA = 2 * ks + (lg >> 1);
    const int ktW = 2 * ks + (lg & 1);
    const uint32_t aRt = (uint32_t)((4 * mG + (lg & 1)) * 128);
    const uint32_t wRt = (uint32_t)((4 * nG + (lg >> 1)) * 128);
    uint32_t aAddrT[2], wAddrT[2];
#pragma unroll
    for (int st = 0; st < 2; ++st) {
        aAddrT[st] = sb + (uint32_t)(st * STAGE_BYTES) + (uint32_t)(ktA * 1024) +
                     (uint32_t)((lr ^ (ktA << 1)) << 4) + aRt;
        wAddrT[st] = sb + (uint32_t)(st * STAGE_BYTES) + WH_OFF + (uint32_t)(ktW * 1024) +
                     (uint32_t)((lr ^ (ktW << 1)) << 4) + wRt;
    }

    // prologue
    ldRegs(0);
    stStage(0);
    ldRegs(1);

#pragma unroll 1
    for (int tb = 0; tb < NCHUNK; tb += 2) {
#pragma unroll
        for (int tt = 0; tt < 2; ++tt) {
            const int t = tb + tt;
            __syncthreads();
            if (t + 1 < NCHUNK) {
                stStage(tt ^ 1);
                if (t + 2 < NCHUNK) ldRegs(t + 2);
            }
            const uint32_t aAddr = aAddrT[tt];
            const uint32_t wAddr = wAddrT[tt];

            uint32_t wh[8], wl[8];
            LDMX4(wh[0], wh[1], wh[2], wh[3], wAddr);
            LDMX4(wh[4], wh[5], wh[6], wh[7], wAddr + 256);
            LDMX4(wl[0], wl[1], wl[2], wl[3], wAddr + 4096);
            LDMX4(wl[4], wl[5], wl[6], wl[7], wAddr + 4096 + 256);

#pragma unroll
            for (int mt = 0; mt < 2; ++mt) {
                uint32_t ah[4], al[4];
                LDMX4(ah[0], ah[1], ah[2], ah[3], aAddr + mt * 256);
                LDMX4(al[0], al[1], al[2], al[3], aAddr + AL_OFF + mt * 256);
#pragma unroll
                for (int nt = 0; nt < 4; ++nt) {
                    const uint32_t bh0 = wh[2 * nt], bh1 = wh[2 * nt + 1];
                    const uint32_t bl0 = wl[2 * nt], bl1 = wl[2 * nt + 1];
                    MMA_BF16(acc[mt][nt], ah[0], ah[1], ah[2], ah[3], bh0, bh1);
                    MMA_BF16(acc[mt][nt], ah[0], ah[1], ah[2], ah[3], bl0, bl1);
                    MMA_BF16(acc[mt][nt], al[0], al[1], al[2], al[3], bh0, bh1);
                }
            }
        }
    }

    // ---- epilogue: two partial-logit copies, then sum ----------------------
    __syncthreads();
    float* Cs = reinterpret_cast<float*>(sbase);      // [2][64][66]
    float* myCs = Cs + ks * (64 * 66);
#pragma unroll
    for (int mt = 0; mt < 2; ++mt)
#pragma unroll
        for (int nt = 0; nt < 4; ++nt) {
            int row = 32 * mG + 16 * mt + g;
            int col = 32 * nG + 8 * nt + 2 * q;
            *reinterpret_cast<float2*>(&myCs[row * 66 + col]) =
                make_float2(acc[mt][nt][0], acc[mt][nt][1]);
            *reinterpret_cast<float2*>(&myCs[(row + 8) * 66 + col]) =
                make_float2(acc[mt][nt][2], acc[mt][nt][3]);
        }
    __syncthreads();

    if (tid < BM) {                     // one thread per token
        const int t = tid;
        float f[64];
        float mx = -1e30f;
#pragma unroll
        for (int e = 0; e < NEXP; e++) {
            f[e] = Cs[t * 66 + e] + Cs[64 * 66 + t * 66 + e];
            mx = fmaxf(mx, f[e]);
        }
        float ssum = 0.f;
#pragma unroll
        for (int e = 0; e < NEXP; e++) { f[e] = expf(f[e] - mx); ssum += f[e]; }
        float inv = 1.0f / ssum;
        float v1 = -1.f, v2 = -1.f;
        int i1 = 0, i2 = 0;
#pragma unroll
        for (int e = 0; e < NEXP; e++) {
            float p = f[e] * inv;
            Cs[t * 66 + e] = p;         // probs into Cs0 for coalesced copy
            if (p > v1)      { v2 = v1; i2 = i1; v1 = p; i1 = e; }
            else if (p > v2) { v2 = p; i2 = e; }
        }
        // combine = softmax over the top-2 prob VALUES (reference quirk)
        float eb = expf(v2 - v1);
        float invd = 1.0f / (1.0f + eb);
        const int token = tok0 + t;
        const int flat = token * 2;
        out[OFF_CW + flat]     = invd;
        out[OFF_CW + flat + 1] = eb * invd;
        g_flat_idx[flat]     = i1;
        g_flat_idx[flat + 1] = i2;
        atomicAdd(&hist[i1], 1);
        atomicAdd(&hist[i2], 1);
    }
    __syncthreads();

    if (tid < NEXP) g_blockHist[blk * NEXP + tid] = hist[tid];

    // coalesced probs writeback
    float* pout = out + OFF_PROBS + (size_t)tok0 * NEXP;
    for (int idx = tid; idx < BM * NEXP; idx += GTHREADS) {
        int tt = idx >> 6, e = idx & 63;
        pout[idx] = Cs[tt * 66 + e];
    }
}

// ---------------------------------------------------------------------------
// Kernel 2 (1 CTA, 1024 threads): per-expert scan across blocks + offsets
// ---------------------------------------------------------------------------
#define CHUNKB (NBLK / 16)       // 16 blocks per chunk
__global__ __launch_bounds__(1024) void gate_scan_kernel(float* __restrict__ out)
{
    __shared__ int part[16][NEXP];
    __shared__ int totals[NEXP];
    __shared__ int offs[NEXP];
    const int tid = threadIdx.x;
    const int e = tid & 63;
    const int c = tid >> 6;          // chunk 0..15

    int s = 0;
#pragma unroll
    for (int b = c * CHUNKB; b < (c + 1) * CHUNKB; b++) s += g_blockHist[b * NEXP + e];
    part[c][e] = s;
    __syncthreads();

    if (tid < NEXP) {
        int run = 0;
#pragma unroll
        for (int cc = 0; cc < 16; cc++) run += part[cc][e];
        totals[e] = run;
        out[OFF_SPL + e] = (float)run;
    }
    __syncthreads();

    if (tid == 0) {
        int a = 0;
        for (int i = 0; i < NEXP; i++) { offs[i] = a; a += totals[i]; }
    }
    __syncthreads();

    int base = offs[e];
    for (int cc = 0; cc < c; cc++) base += part[cc][e];
#pragma unroll
    for (int b = c * CHUNKB; b < (c + 1) * CHUNKB; b++) {
        g_blockBase[b * NEXP + e] = base;
        base += g_blockHist[b * NEXP + e];
    }
}

// ---------------------------------------------------------------------------
// Kernel 3 (NBLK x 128): stable intra-block rank + scatter.
// ---------------------------------------------------------------------------
__global__ __launch_bounds__(128) void gate_scatter_kernel(float* __restrict__ out)
{
    __shared__ int warpHist[4][NEXP];
    __shared__ int base_s[NEXP];
    const int tid  = threadIdx.x;
    const int blk  = blockIdx.x;
    const int w    = tid >> 5;
    const int lane = tid & 31;

    if (tid < NEXP) base_s[tid] = g_blockBase[blk * NEXP + tid];
    for (int i = tid; i < 4 * NEXP; i += 128) (&warpHist[0][0])[i] = 0;
    __syncthreads();

    const int flat = blk * 128 + tid;
    const int e    = g_flat_idx[flat];

    unsigned m     = __match_any_sync(0xffffffffu, e);
    unsigned below = m & ((1u << lane) - 1u);
    int rank = __popc(below);
    if (below == 0) warpHist[w][e] = __popc(m);     // lowest lane of group
    __syncthreads();

    int prev = 0;
#pragma unroll
    for (int ww = 0; ww < 3; ++ww)
        if (ww < w) prev += warpHist[ww][e];

    const int pos = base_s[e] + prev + rank;
    out[OFF_TOK + pos]  = (float)(flat >> 1);       // token index
    out[OFF_REV + flat] = (float)pos;               // sorted position of flat idx
}

// ---------------------------------------------------------------------------
extern "C" void kernel_launch(void* const* d_in, const int* in_sizes, int n_in,
                              void* d_out, int out_size)
{
    const float* A = (const float*)d_in[0];   // inputs    [16384, 2048] fp32
    const float* W = (const float*)d_in[1];   // wg_weight [64, 2048]    fp32
    float* out = (float*)d_out;

    cudaFuncSetAttribute(gate_gemm_kernel,
                         cudaFuncAttributeMaxDynamicSharedMemorySize, SMEM_DYN);

    gate_gemm_kernel<<<NBLK, GTHREADS, SMEM_DYN>>>(A, W, out);
    gate_scan_kernel<<<1, 1024>>>(out);
    gate_scatter_kernel<<<NK / 128, 128>>>(out);
}

// round 17
// speedup vs baseline: 1.9059x; 1.0660x over previous
#include <cuda_runtime.h>
#include <cuda_bf16.h>
#include <math.h>
#include <stdint.h>

// Problem constants
#define NTOK 16384
#define DIM  2048
#define NEXP 64
#define NK   (NTOK * 2)          // 32768 (token, slot) pairs

// GEMM tiling
#define BM 64                    // tokens per CTA
#define KC 64                    // fp32 per K-chunk (4 k16 steps, 2 per ks warp)
#define NCHUNK (DIM / KC)        // 32
#define GTHREADS 256             // 8 warps: (ks, mG, nG) each M32 x N32 x k32
#define NBLK (NTOK / BM)         // 256 CTAs

// Output layout: concatenation of reference return values (all as fp32)
#define OFF_TOK   0
#define OFF_REV   NK
#define OFF_CW    (2 * NK)
#define OFF_SPL   (3 * NK)
#define OFF_PROBS (3 * NK + NEXP)

// smem stage layout (bytes): blocked 8x8-bf16 tiles (128B each), 64 tiles per
// half (8 kt x 8 rt).
#define AH_OFF 0
#define AL_OFF 8192
#define WH_OFF 16384
#define WL_OFF 24576
#define STAGE_BYTES 32768
#define SMEM_DYN (2 * STAGE_BYTES + 2048)

// Scratch (no allocations allowed -> __device__ globals)
__device__ int g_flat_idx[NK];
__device__ int g_blockHist[NBLK * NEXP];
__device__ int g_blockBase[NBLK * NEXP];

// ---------------------------------------------------------------------------
__device__ __forceinline__ uint32_t smem_u32(const void* p) {
    uint32_t a;
    asm("{ .reg .u64 t; cvta.to.shared.u64 t, %1; cvt.u32.u64 %0, t; }"
        : "=r"(a) : "l"(p));
    return a;
}

#define LDMX4(r0, r1, r2, r3, addr)                                           \
    asm volatile("ldmatrix.sync.aligned.m8n8.x4.shared.b16 {%0,%1,%2,%3}, [%4];" \
        : "=r"(r0), "=r"(r1), "=r"(r2), "=r"(r3) : "r"(addr))

#define MMA_BF16(c, a0, a1, a2, a3, b0, b1)                                   \
    asm volatile(                                                             \
        "mma.sync.aligned.m16n8k16.row.col.f32.bf16.bf16.f32 "                \
        "{%0,%1,%2,%3}, {%4,%5,%6,%7}, {%8,%9}, {%0,%1,%2,%3};"               \
        : "+f"((c)[0]), "+f"((c)[1]), "+f"((c)[2]), "+f"((c)[3])              \
        : "r"(a0), "r"(a1), "r"(a2), "r"(a3), "r"(b0), "r"(b1))

__device__ __forceinline__ uint32_t pack_bf16(__nv_bfloat16 a, __nv_bfloat16 b) {
    __nv_bfloat162 v; v.x = a; v.y = b;
    return *reinterpret_cast<uint32_t*>(&v);
}

__device__ __forceinline__ void split2(float x, float y, uint32_t& hi, uint32_t& lo) {
    __nv_bfloat16 hx = __float2bfloat16(x), hy = __float2bfloat16(y);
    float rx = x - __bfloat162float(hx);
    float ry = y - __bfloat162float(hy);
    hi = pack_bf16(hx, hy);
    lo = pack_bf16(__float2bfloat16(rx), __float2bfloat16(ry));
}

// ---------------------------------------------------------------------------
// Kernel 1: ks-split bf16 GEMM, KC=64 (32 chunks, 32 barriers).
// 8 warps = (ks = wid>>2) x (mG = (wid>>1)&1) x (nG = wid&1); each warp owns
// M32 x N32 x its k32 half (2 k16 sub-steps) of every chunk.
// ---------------------------------------------------------------------------
__global__ __launch_bounds__(GTHREADS, 2) void gate_gemm_kernel(
    const float* __restrict__ A,   // [NTOK, DIM]
    const float* __restrict__ W,   // [NEXP, DIM]
    float* __restrict__ out)
{
    extern __shared__ char dynsm[];
    char* sbase = (char*)(((uintptr_t)dynsm + 1023) & ~(uintptr_t)1023);
    const uint32_t sb = smem_u32(sbase);

    __shared__ int hist[NEXP];

    const int tid  = threadIdx.x;
    const int wid  = tid >> 5;
    const int lane = tid & 31;
    const int g    = lane >> 2;
    const int q    = lane & 3;
    const int lg   = lane >> 3;       // ldmatrix lane group 0..3
    const int lr   = lane & 7;
    const int ks   = wid >> 2;        // k32 half owned by this warp
    const int mG   = (wid >> 1) & 1;  // rows 32*mG
    const int nG   = wid & 1;         // cols 32*nG
    const int blk  = blockIdx.x;
    const int tok0 = blk * BM;

    if (tid < NEXP) hist[tid] = 0;

    // ---- producer geometry: warp = 4 rows x 128B contiguous per LDG --------
    const int prow = tid >> 3;        // 0..31
    const int c4   = tid & 7;

    const float4* Ap[2];
    const float4* Wp[2];
    uint32_t stOff[2][2];             // [p][ch]
#pragma unroll
    for (int p = 0; p < 2; ++p) {
        int r = prow + 32 * p;        // 0..63
        Ap[p] = reinterpret_cast<const float4*>(A + (size_t)(tok0 + r) * DIM + 4 * c4);
        Wp[p] = reinterpret_cast<const float4*>(W + (size_t)r * DIM + 4 * c4);
#pragma unroll
        for (int ch = 0; ch < 2; ++ch) {
            int j  = c4 + 8 * ch;     // float4 index within 64-float chunk row
            int kt = j >> 1;          // 0..7
            int hf = j & 1;
            stOff[p][ch] = (uint32_t)((kt * 8 + (r >> 3)) * 128 +
                                      (((r & 7) ^ ((kt & 3) << 1)) << 4) + hf * 8);
        }
    }

    float4 pa[2][2], pw[2][2];
    auto ldRegs = [&](int t) {
        const int o = t * 16;         // 64 floats = 16 float4 per chunk row
#pragma unroll
        for (int p = 0; p < 2; ++p)
#pragma unroll
            for (int ch = 0; ch < 2; ++ch) {
                pa[p][ch] = Ap[p][o + 8 * ch];
                pw[p][ch] = Wp[p][o + 8 * ch];
            }
    };
    auto stStage = [&](int s) {
        char* stg = sbase + s * STAGE_BYTES;
#pragma unroll
        for (int p = 0; p < 2; ++p)
#pragma unroll
            for (int ch = 0; ch < 2; ++ch) {
                uint2 h, l;
                split2(pa[p][ch].x, pa[p][ch].y, h.x, l.x);
                split2(pa[p][ch].z, pa[p][ch].w, h.y, l.y);
                *reinterpret_cast<uint2*>(stg + AH_OFF + stOff[p][ch]) = h;
                *reinterpret_cast<uint2*>(stg + AL_OFF + stOff[p][ch]) = l;
                split2(pw[p][ch].x, pw[p][ch].y, h.x, l.x);
                split2(pw[p][ch].z, pw[p][ch].w, h.y, l.y);
                *reinterpret_cast<uint2*>(stg + WH_OFF + stOff[p][ch]) = h;
                *reinterpret_cast<uint2*>(stg + WL_OFF + stOff[p][ch]) = l;
            }
    };

    float acc[2][4][4];               // [mt][nt][c]
#pragma unroll
    for (int mt = 0; mt < 2; ++mt)
#pragma unroll
        for (int nt = 0; nt < 4; ++nt)
#pragma unroll
            for (int c = 0; c < 4; ++c) acc[mt][nt][c] = 0.f;

    // ---- precomputed consumer addresses: [stage][sub] ----------------------
    const uint32_t aRt = (uint32_t)((4 * mG + (lg & 1)) * 128);
    const uint32_t wRt = (uint32_t)((4 * nG + (lg >> 1)) * 128);
    uint32_t aAddrT[2][2], wAddrT[2][2];
#pragma unroll
    for (int st = 0; st < 2; ++st)
#pragma unroll
        for (int sub = 0; sub < 2; ++sub) {
            const int ktA = 4 * ks + 2 * sub + (lg >> 1);
            const int ktW = 4 * ks + 2 * sub + (lg & 1);
            aAddrT[st][sub] = sb + (uint32_t)(st * STAGE_BYTES) +
                              (uint32_t)(ktA * 1024) +
                              (uint32_t)((lr ^ ((ktA & 3) << 1)) << 4) + aRt;
            wAddrT[st][sub] = sb + (uint32_t)(st * STAGE_BYTES) + WH_OFF +
                              (uint32_t)(ktW * 1024) +
                              (uint32_t)((lr ^ ((ktW & 3) << 1)) << 4) + wRt;
        }

    // prologue
    ldRegs(0);
    stStage(0);
    ldRegs(1);

#pragma unroll 1
    for (int tb = 0; tb < NCHUNK; tb += 2) {
#pragma unroll
        for (int tt = 0; tt < 2; ++tt) {
            const int t = tb + tt;
            __syncthreads();
            if (t + 1 < NCHUNK) {
                stStage(tt ^ 1);
                if (t + 2 < NCHUNK) ldRegs(t + 2);
            }
#pragma unroll
            for (int sub = 0; sub < 2; ++sub) {
                const uint32_t aAddr = aAddrT[tt][sub];
                const uint32_t wAddr = wAddrT[tt][sub];

                uint32_t wh[8], wl[8];
                LDMX4(wh[0], wh[1], wh[2], wh[3], wAddr);
                LDMX4(wh[4], wh[5], wh[6], wh[7], wAddr + 256);
                LDMX4(wl[0], wl[1], wl[2], wl[3], wAddr + 8192);
                LDMX4(wl[4], wl[5], wl[6], wl[7], wAddr + 8192 + 256);

#pragma unroll
                for (int mt = 0; mt < 2; ++mt) {
                    uint32_t ah[4], al[4];
                    LDMX4(ah[0], ah[1], ah[2], ah[3], aAddr + mt * 256);
                    LDMX4(al[0], al[1], al[2], al[3], aAddr + 8192 + mt * 256);
#pragma unroll
                    for (int nt = 0; nt < 4; ++nt) {
                        const uint32_t bh0 = wh[2 * nt], bh1 = wh[2 * nt + 1];
                        const uint32_t bl0 = wl[2 * nt], bl1 = wl[2 * nt + 1];
                        MMA_BF16(acc[mt][nt], ah[0], ah[1], ah[2], ah[3], bh0, bh1);
                        MMA_BF16(acc[mt][nt], ah[0], ah[1], ah[2], ah[3], bl0, bl1);
                        MMA_BF16(acc[mt][nt], al[0], al[1], al[2], al[3], bh0, bh1);
                    }
                }
            }
        }
    }

    // ---- epilogue: two partial-logit copies, then sum ----------------------
    __syncthreads();
    float* Cs = reinterpret_cast<float*>(sbase);      // [2][64][66]
    float* myCs = Cs + ks * (64 * 66);
#pragma unroll
    for (int mt = 0; mt < 2; ++mt)
#pragma unroll
        for (int nt = 0; nt < 4; ++nt) {
            int row = 32 * mG + 16 * mt + g;
            int col = 32 * nG + 8 * nt + 2 * q;
            *reinterpret_cast<float2*>(&myCs[row * 66 + col]) =
                make_float2(acc[mt][nt][0], acc[mt][nt][1]);
            *reinterpret_cast<float2*>(&myCs[(row + 8) * 66 + col]) =
                make_float2(acc[mt][nt][2], acc[mt][nt][3]);
        }
    __syncthreads();

    if (tid < BM) {                     // one thread per token
        const int t = tid;
        float f[64];
        float mx = -1e30f;
#pragma unroll
        for (int e = 0; e < NEXP; e++) {
            f[e] = Cs[t * 66 + e] + Cs[64 * 66 + t * 66 + e];
            mx = fmaxf(mx, f[e]);
        }
        float ssum = 0.f;
#pragma unroll
        for (int e = 0; e < NEXP; e++) { f[e] = expf(f[e] - mx); ssum += f[e]; }
        float inv = 1.0f / ssum;
        float v1 = -1.f, v2 = -1.f;
        int i1 = 0, i2 = 0;
#pragma unroll
        for (int e = 0; e < NEXP; e++) {
            float p = f[e] * inv;
            Cs[t * 66 + e] = p;         // probs into Cs0 for coalesced copy
            if (p > v1)      { v2 = v1; i2 = i1; v1 = p; i1 = e; }
            else if (p > v2) { v2 = p; i2 = e; }
        }
        // combine = softmax over the top-2 prob VALUES (reference quirk)
        float eb = expf(v2 - v1);
        float invd = 1.0f / (1.0f + eb);
        const int token = tok0 + t;
        const int flat = token * 2;
        out[OFF_CW + flat]     = invd;
        out[OFF_CW + flat + 1] = eb * invd;
        g_flat_idx[flat]     = i1;
        g_flat_idx[flat + 1] = i2;
        atomicAdd(&hist[i1], 1);
        atomicAdd(&hist[i2], 1);
    }
    __syncthreads();

    if (tid < NEXP) g_blockHist[blk * NEXP + tid] = hist[tid];

    // coalesced probs writeback
    float* pout = out + OFF_PROBS + (size_t)tok0 * NEXP;
    for (int idx = tid; idx < BM * NEXP; idx += GTHREADS) {
        int tt = idx >> 6, e = idx & 63;
        pout[idx] = Cs[tt * 66 + e];
    }
}

// ---------------------------------------------------------------------------
// Kernel 2 (1 CTA, 1024 threads): per-expert scan across blocks + offsets
// ---------------------------------------------------------------------------
#define CHUNKB (NBLK / 16)       // 16 blocks per chunk
__global__ __launch_bounds__(1024) void gate_scan_kernel(float* __restrict__ out)
{
    __shared__ int part[16][NEXP];
    __shared__ int totals[NEXP];
    __shared__ int offs[NEXP];
    const int tid = threadIdx.x;
    const int e = tid & 63;
    const int c = tid >> 6;          // chunk 0..15

    int s = 0;
#pragma unroll
    for (int b = c * CHUNKB; b < (c + 1) * CHUNKB; b++) s += g_blockHist[b * NEXP + e];
    part[c][e] = s;
    __syncthreads();

    if (tid < NEXP) {
        int run = 0;
#pragma unroll
        for (int cc = 0; cc < 16; cc++) run += part[cc][e];
        totals[e] = run;
        out[OFF_SPL + e] = (float)run;
    }
    __syncthreads();

    if (tid == 0) {
        int a = 0;
        for (int i = 0; i < NEXP; i++) { offs[i] = a; a += totals[i]; }
    }
    __syncthreads();

    int base = offs[e];
    for (int cc = 0; cc < c; cc++) base += part[cc][e];
#pragma unroll
    for (int b = c * CHUNKB; b < (c + 1) * CHUNKB; b++) {
        g_blockBase[b * NEXP + e] = base;
        base += g_blockHist[b * NEXP + e];
    }
}

// ---------------------------------------------------------------------------
// Kernel 3 (NBLK x 128): stable intra-block rank + scatter.
// ---------------------------------------------------------------------------
__global__ __launch_bounds__(128) void gate_scatter_kernel(float* __restrict__ out)
{
    __shared__ int warpHist[4][NEXP];
    __shared__ int base_s[NEXP];
    const int tid  = threadIdx.x;
    const int blk  = blockIdx.x;
    const int w    = tid >> 5;
    const int lane = tid & 31;

    if (tid < NEXP) base_s[tid] = g_blockBase[blk * NEXP + tid];
    for (int i = tid; i < 4 * NEXP; i += 128) (&warpHist[0][0])[i] = 0;
    __syncthreads();

    const int flat = blk * 128 + tid;
    const int e    = g_flat_idx[flat];

    unsigned m     = __match_any_sync(0xffffffffu, e);
    unsigned below = m & ((1u << lane) - 1u);
    int rank = __popc(below);
    if (below == 0) warpHist[w][e] = __popc(m);     // lowest lane of group
    __syncthreads();

    int prev = 0;
#pragma unroll
    for (int ww = 0; ww < 3; ++ww)
        if (ww < w) prev += warpHist[ww][e];

    const int pos = base_s[e] + prev + rank;
    out[OFF_TOK + pos]  = (float)(flat >> 1);       // token index
    out[OFF_REV + flat] = (float)pos;               // sorted position of flat idx
}

// ---------------------------------------------------------------------------
extern "C" void kernel_launch(void* const* d_in, const int* in_sizes, int n_in,
                              void* d_out, int out_size)
{
    const float* A = (const float*)d_in[0];   // inputs    [16384, 2048] fp32
    const float* W = (const float*)d_in[1];   // wg_weight [64, 2048]    fp32
    float* out = (float*)d_out;

    cudaFuncSetAttribute(gate_gemm_kernel,
                         cudaFuncAttributeMaxDynamicSharedMemorySize, SMEM_DYN);

    gate_gemm_kernel<<<NBLK, GTHREADS, SMEM_DYN>>>(A, W, out);
    gate_scan_kernel<<<1, 1024>>>(out);
    gate_scatter_kernel<<<NK / 128, 128>>>(out);
}